// round 7
// baseline (speedup 1.0000x reference)
#include <cuda_runtime.h>
#include <math.h>

#define T_LEN 32
#define KP    2048
#define CPB   14                       // columns per block
#define GPC   16                       // threads per column
#define BLOCK (CPB * GPC)              // 224 threads, 7 warps
#define GRID  147                      // ceil(2048/14); <= 148 SMs -> all co-resident

// sp = sqrt(1/32); 0.5/sp^2 = 16 exactly
#define LOG_SP     (-1.7328679513998633f)
#define HALF_L2PI  (0.9189385332046727f)
#define LOG_K      (7.6246189861593985f)
#define C2EXP      (-23.083120654223414f)   // -16 * log2(e)
#define L2E        (1.4426950408889634f)
#define F_INF      (__int_as_float(0x7f800000))

__device__ float g_zs[T_LEN * KP];
__device__ float g_A [T_LEN * KP];
__device__ float g_rb[T_LEN][KP];     // r per step (fresh address each step: no stale L1)
__device__ int   g_xmax[T_LEN];       // order-encoded float max of r at step t
__device__ int   g_bar_count;
__device__ int   g_bar_epoch;

__device__ __forceinline__ int   fenc(float f) { int b = __float_as_int(f); return b >= 0 ? b : (b ^ 0x7fffffff); }
__device__ __forceinline__ float fdec(int e)   { return __int_as_float(e >= 0 ? e : (e ^ 0x7fffffff)); }

// scalar fast 2^t for t <= 0, FMA/ALU pipes only
__device__ __forceinline__ float fexp2(float t) {
    t = fmaxf(t, -126.0f);
    float fn = t + 12582912.0f;
    int   n  = __float_as_int(fn) - 0x4B400000;
    float f  = t - (fn - 12582912.0f);
    float p  = 1.3398874e-3f;
    p = fmaf(p, f, 9.6184374e-3f);
    p = fmaf(p, f, 5.5503325e-2f);
    p = fmaf(p, f, 2.4022648e-1f);
    p = fmaf(p, f, 6.9314720e-1f);
    p = fmaf(p, f, 1.0f);
    return __int_as_float(__float_as_int(p) + (n << 23));
}

// packed f32x2 ops (sm_103a)
#define F2ADD(o,a,b)   asm("add.rn.f32x2 %0,%1,%2;"    : "=l"(o) : "l"(a), "l"(b))
#define F2MUL(o,a,b)   asm("mul.rn.f32x2 %0,%1,%2;"    : "=l"(o) : "l"(a), "l"(b))
#define F2FMA(o,a,b,c) asm("fma.rn.f32x2 %0,%1,%2,%3;" : "=l"(o) : "l"(a), "l"(b), "l"(c))

__device__ __forceinline__ unsigned long long f2pk(float lo, float hi) {
    unsigned long long r; asm("mov.b64 %0,{%1,%2};" : "=l"(r) : "f"(lo), "f"(hi)); return r;
}
__device__ __forceinline__ unsigned long long u2pk(unsigned lo, unsigned hi) {
    unsigned long long r; asm("mov.b64 %0,{%1,%2};" : "=l"(r) : "r"(lo), "r"(hi)); return r;
}

__global__ void init_kernel() {
    int i = threadIdx.x;
    if (i < T_LEN) g_xmax[i] = fenc(-F_INF);
    if (i == 32) { g_bar_count = 0; g_bar_epoch = -1; }
}

// grid-wide barrier: all CTAs co-resident (GRID <= #SMs). One epoch per step.
__device__ __forceinline__ void grid_bar(int target) {
    __threadfence();
    __syncthreads();
    if (threadIdx.x == 0) {
        int old = atomicAdd(&g_bar_count, 1);
        if (old == GRID - 1) {
            atomicExch(&g_bar_count, 0);
            __threadfence();
            atomicExch(&g_bar_epoch, target);
        } else {
            while (*(volatile int*)&g_bar_epoch < target) {}
        }
    }
    __syncthreads();
}

__global__ void __launch_bounds__(BLOCK) main_kernel(const float* __restrict__ means,
                                                     const float* __restrict__ log_stds,
                                                     const float* __restrict__ eps,
                                                     float* __restrict__ out) {
    __shared__ __align__(16) float lz[KP];    // -z_{t-1}
    __shared__ __align__(16) float lu[KP];    // (r_j - x) * log2e
    __shared__ float wred[CPB];
    __shared__ float red[8];

    const int tid = threadIdx.x;

    // ---- fused setup: zs, A, r0, max(r0) ----
    #pragma unroll
    for (int s = 0; s < 2; s++) {
        int idx = blockIdx.x * BLOCK + tid + s * (GRID * BLOCK);
        float r0v = -F_INF;
        if (idx < T_LEN * KP) {
            int t = idx / KP;
            int k = idx - t * KP;
            float mu = means[t];
            float sg = expf(log_stds[t]);
            float z  = fmaf(sg, eps[idx], mu);
            float zq = (z - mu) / sg;
            float lq = fmaf(-0.5f * zq, zq, -logf(sg)) - HALF_L2PI;
            g_zs[idx] = z;
            g_A[idx]  = -LOG_SP - HALF_L2PI - lq;
            if (t == 0) {
                float zz = z * 5.656854249492380f;   // z / sp
                r0v = fmaf(-0.5f * zz, zz, -LOG_SP) - HALF_L2PI - lq;
                g_rb[0][k] = r0v;
            }
        }
        float m = r0v;
        #pragma unroll
        for (int sft = 16; sft; sft >>= 1)
            m = fmaxf(m, __shfl_xor_sync(0xffffffffu, m, sft));
        if ((tid & 31) == 0) atomicMax(&g_xmax[0], fenc(m));
    }
    grid_bar(0);

    // ---- 31 fused scan steps ----
    const int cloc = tid >> 4;                 // column-in-block 0..13
    const int g    = tid & (GPC - 1);
    const int k    = blockIdx.x * CPB + cloc;

    for (int t = 1; t < T_LEN; t++) {
        const float x = fdec(__ldcg(&g_xmax[t - 1]));
        const float* __restrict__ zrow = g_zs + (t - 1) * KP;
        if (tid < CPB) wred[tid] = -F_INF;
        for (int j = tid; j < KP; j += BLOCK) {
            float rv = __ldcg(&g_rb[t - 1][j]);
            lu[j] = (rv - x) * L2E;
            lz[j] = -zrow[j];
        }
        __syncthreads();

        if (k < KP) {
            const float zk = __ldcg(&g_zs[t * KP + k]);
            const float ak = __ldcg(&g_A [t * KP + k]);
            const unsigned long long zk2  = f2pk(zk, zk);
            const unsigned long long c2v  = f2pk(C2EXP, C2EXP);
            const unsigned long long bigv = f2pk(12582912.0f, 12582912.0f);
            const unsigned long long m1v  = f2pk(-1.0f, -1.0f);
            const unsigned long long c5v  = f2pk(1.3398874e-3f, 1.3398874e-3f);
            const unsigned long long c4v  = f2pk(9.6184374e-3f, 9.6184374e-3f);
            const unsigned long long c3v  = f2pk(5.5503325e-2f, 5.5503325e-2f);
            const unsigned long long c2pv = f2pk(2.4022648e-1f, 2.4022648e-1f);
            const unsigned long long c1v  = f2pk(6.9314720e-1f, 6.9314720e-1f);
            const unsigned long long c0v  = f2pk(1.0f, 1.0f);

            unsigned long long S2 = 0ULL;
            #pragma unroll 8
            for (int i = 0; i < KP / (2 * GPC); i++) {
                int jj = i * GPC + g;                    // float2 index
                unsigned long long zu = *reinterpret_cast<const unsigned long long*>(lz + 2 * jj);
                unsigned long long uu = *reinterpret_cast<const unsigned long long*>(lu + 2 * jj);
                unsigned long long d, dd, tt, fn, nn, f, p;
                F2ADD(d, zk2, zu);                       // d = zk - z'
                F2MUL(dd, d, d);
                F2FMA(tt, dd, c2v, uu);                  // t = C2*d^2 + log2(u)  (<= 0)
                float t0 = fmaxf(__uint_as_float((unsigned)tt),         -126.0f);
                float t1 = fmaxf(__uint_as_float((unsigned)(tt >> 32)), -126.0f);
                tt = f2pk(t0, t1);
                F2ADD(fn, tt, bigv);
                F2FMA(nn, fn, m1v, bigv);                // nn = big - fn = -n
                F2ADD(f, tt, nn);                        // f = t - n
                F2FMA(p, c5v, f, c4v);
                F2FMA(p, p,   f, c3v);
                F2FMA(p, p,   f, c2pv);
                F2FMA(p, p,   f, c1v);
                F2FMA(p, p,   f, c0v);                   // p ~= 2^f
                unsigned fnl = (unsigned)fn, fnh = (unsigned)(fn >> 32);
                unsigned pl  = (unsigned)p,  ph  = (unsigned)(p  >> 32);
                unsigned long long ev = u2pk(pl + (fnl << 23), ph + (fnh << 23));  // 2^f * 2^n
                F2ADD(S2, S2, ev);
            }
            float S = __uint_as_float((unsigned)S2) + __uint_as_float((unsigned)(S2 >> 32));
            #pragma unroll
            for (int m = GPC / 2; m; m >>= 1)
                S += __shfl_xor_sync(0xffffffffu, S, m, GPC);
            if (g == 0) {
                float val = x + ak + logf(fmaxf(S, 1e-37f)) - LOG_K;
                __stcg(&g_rb[t][k], val);
                wred[cloc] = val;
            }
        }
        __syncthreads();
        if (tid == 0) {
            float m = wred[0];
            #pragma unroll
            for (int w = 1; w < CPB; w++) m = fmaxf(m, wred[w]);
            atomicMax(&g_xmax[t], fenc(m));
        }
        grid_bar(t);
    }

    // ---- final: out = x + y + log(sum_j exp(r_j - x) * exp(L_j - y)) - logK ----
    if (blockIdx.x != 0) return;
    const float x = fdec(__ldcg(&g_xmax[T_LEN - 1]));
    float ly = -F_INF;
    for (int j = tid; j < KP; j += BLOCK) {
        float z  = g_zs[(T_LEN - 1) * KP + j];
        float dd = 0.5f - z;
        float Lv = fmaf(-0.5f * dd, dd, -HALF_L2PI);
        lz[j] = Lv;
        lu[j] = __ldcg(&g_rb[T_LEN - 1][j]);
        ly = fmaxf(ly, Lv);
    }
    #pragma unroll
    for (int m = 16; m; m >>= 1)
        ly = fmaxf(ly, __shfl_xor_sync(0xffffffffu, ly, m));
    if ((tid & 31) == 0) red[tid >> 5] = ly;
    __syncthreads();
    float y = red[0];
    #pragma unroll
    for (int w = 1; w < BLOCK / 32; w++) y = fmaxf(y, red[w]);

    float S = 0.0f;
    for (int j = tid; j < KP; j += BLOCK)
        S += fexp2(((lu[j] - x) + (lz[j] - y)) * L2E);
    #pragma unroll
    for (int m = 16; m; m >>= 1)
        S += __shfl_xor_sync(0xffffffffu, S, m);
    if ((tid & 31) == 0) red[tid >> 5] = S;
    __syncthreads();
    if (tid == 0) {
        float tot = 0.0f;
        #pragma unroll
        for (int w = 0; w < BLOCK / 32; w++) tot += red[w];
        out[0] = x + y + logf(tot) - LOG_K;
    }
}

extern "C" void kernel_launch(void* const* d_in, const int* in_sizes, int n_in,
                              void* d_out, int out_size) {
    const float* means    = (const float*)d_in[0];
    const float* log_stds = (const float*)d_in[1];
    const float* eps      = (const float*)d_in[2];
    float* out = (float*)d_out;

    init_kernel<<<1, 64>>>();
    main_kernel<<<GRID, BLOCK>>>(means, log_stds, eps, out);
}